// round 1
// baseline (speedup 1.0000x reference)
#include <cuda_runtime.h>
#include <math.h>

#define Bc   2
#define Sc   2048
#define HIDc 1024
#define NHc  16
#define HDc  64
#define BSc  (Bc * Sc)          // 4096 rows for projections
#define BHc  (Bc * NHc)         // 32 (b,h) slices

// Scratch (device globals — no allocation allowed)
__device__ float g_Q[(size_t)BHc * Sc * HDc];   // [B,NH,S,HD]
__device__ float g_K[(size_t)BHc * Sc * HDc];
__device__ float g_V[(size_t)BHc * Sc * HDc];
__device__ float g_O[(size_t)Bc  * Sc * HIDc];  // attention output, [B,S,HID]

// ---------------------------------------------------------------------------
// Generic NT GEMM: C[M,N] = A[M,K] @ W[N,K]^T + bias[N]
// 64x64 block tile, BK=16, 256 threads, 4x4 register tile per thread.
// PERMUTE=true: scatter output into [B,NH,S,HD] head-major layout.
// ---------------------------------------------------------------------------
template<bool PERMUTE>
__global__ __launch_bounds__(256) void gemm_nt_kernel(
    const float* __restrict__ A, const float* __restrict__ W,
    const float* __restrict__ bias, float* __restrict__ C,
    int M, int N, int K)
{
    __shared__ float As[16][68];   // [k][m], stride 68: 16B-aligned rows, reduced conflicts
    __shared__ float Bs[16][68];   // [k][n]

    const int tid  = threadIdx.x;
    const int lrow = tid >> 2;            // 0..63
    const int lk   = (tid & 3) << 2;      // 0,4,8,12
    const int m0   = blockIdx.x * 64;
    const int n0   = blockIdx.y * 64;
    const int tm   = (tid >> 4) << 2;     // 0..60
    const int tn   = (tid & 15) << 2;     // 0..60

    float acc[4][4] = {};
    const float* Arow = A + (size_t)(m0 + lrow) * K + lk;
    const float* Wrow = W + (size_t)(n0 + lrow) * K + lk;

    for (int k0 = 0; k0 < K; k0 += 16) {
        float4 a = *(const float4*)(Arow + k0);
        float4 b = *(const float4*)(Wrow + k0);
        As[lk+0][lrow] = a.x; As[lk+1][lrow] = a.y;
        As[lk+2][lrow] = a.z; As[lk+3][lrow] = a.w;
        Bs[lk+0][lrow] = b.x; Bs[lk+1][lrow] = b.y;
        Bs[lk+2][lrow] = b.z; Bs[lk+3][lrow] = b.w;
        __syncthreads();
        #pragma unroll
        for (int k = 0; k < 16; ++k) {
            float4 av = *(const float4*)&As[k][tm];
            float4 bv = *(const float4*)&Bs[k][tn];
            float ar[4] = {av.x, av.y, av.z, av.w};
            float br[4] = {bv.x, bv.y, bv.z, bv.w};
            #pragma unroll
            for (int i = 0; i < 4; ++i)
                #pragma unroll
                for (int j = 0; j < 4; ++j)
                    acc[i][j] = fmaf(ar[i], br[j], acc[i][j]);
        }
        __syncthreads();
    }

    #pragma unroll
    for (int i = 0; i < 4; ++i) {
        int m = m0 + tm + i;
        #pragma unroll
        for (int j = 0; j < 4; ++j) {
            int n = n0 + tn + j;
            float v = acc[i][j] + bias[n];
            if (PERMUTE) {
                int b = m / Sc, s = m % Sc;
                int h = n / HDc, d = n % HDc;
                C[(((size_t)(b * NHc + h)) * Sc + s) * HDc + d] = v;
            } else {
                C[(size_t)m * N + n] = v;
            }
        }
    }
}

// ---------------------------------------------------------------------------
// Scores: per (b,h): scores[q,k] = (Q·K)/8 + beta*sim[b,q,k], masked.
// K-dim = HD = 64 (4 tiles of 16). Output -> attention-weights region of d_out.
// ---------------------------------------------------------------------------
__global__ __launch_bounds__(256) void scores_kernel(
    const float* __restrict__ sim, const int* __restrict__ mask,
    const float* __restrict__ beta_p, float* __restrict__ scores)
{
    __shared__ float As[16][68];
    __shared__ float Bs[16][68];

    const int bh = blockIdx.z;             // 0..31
    const int b  = bh / NHc;
    const float* Q  = g_Q + (size_t)bh * Sc * HDc;
    const float* Kp = g_K + (size_t)bh * Sc * HDc;

    const int tid  = threadIdx.x;
    const int lrow = tid >> 2;
    const int lk   = (tid & 3) << 2;
    const int m0   = blockIdx.x * 64;
    const int n0   = blockIdx.y * 64;
    const int tm   = (tid >> 4) << 2;
    const int tn   = (tid & 15) << 2;

    float acc[4][4] = {};
    const float* Arow = Q  + (size_t)(m0 + lrow) * HDc + lk;
    const float* Wrow = Kp + (size_t)(n0 + lrow) * HDc + lk;

    #pragma unroll
    for (int k0 = 0; k0 < HDc; k0 += 16) {
        float4 a = *(const float4*)(Arow + k0);
        float4 bv4 = *(const float4*)(Wrow + k0);
        As[lk+0][lrow] = a.x;   As[lk+1][lrow] = a.y;
        As[lk+2][lrow] = a.z;   As[lk+3][lrow] = a.w;
        Bs[lk+0][lrow] = bv4.x; Bs[lk+1][lrow] = bv4.y;
        Bs[lk+2][lrow] = bv4.z; Bs[lk+3][lrow] = bv4.w;
        __syncthreads();
        #pragma unroll
        for (int k = 0; k < 16; ++k) {
            float4 av = *(const float4*)&As[k][tm];
            float4 bv = *(const float4*)&Bs[k][tn];
            float ar[4] = {av.x, av.y, av.z, av.w};
            float br[4] = {bv.x, bv.y, bv.z, bv.w};
            #pragma unroll
            for (int i = 0; i < 4; ++i)
                #pragma unroll
                for (int j = 0; j < 4; ++j)
                    acc[i][j] = fmaf(ar[i], br[j], acc[i][j]);
        }
        __syncthreads();
    }

    const float beta = *beta_p;
    #pragma unroll
    for (int i = 0; i < 4; ++i) {
        int m = m0 + tm + i;
        #pragma unroll
        for (int j = 0; j < 4; ++j) {
            int n = n0 + tn + j;
            float v = acc[i][j] * 0.125f
                    + beta * sim[((size_t)b * Sc + m) * Sc + n];
            if (mask[b * Sc + n] == 0) v = -1e30f;
            scores[(((size_t)bh) * Sc + m) * Sc + n] = v;
        }
    }
}

// ---------------------------------------------------------------------------
// Row softmax in-place over the attention-weights region. One block per row.
// ---------------------------------------------------------------------------
__global__ __launch_bounds__(256) void softmax_kernel(float* __restrict__ data)
{
    const size_t row = blockIdx.x;
    float* p = data + row * (size_t)Sc;
    const int t = threadIdx.x;

    float vals[8];
    float m = -INFINITY;
    #pragma unroll
    for (int i = 0; i < 8; ++i) {
        vals[i] = p[t + i * 256];
        m = fmaxf(m, vals[i]);
    }

    __shared__ float red_max[8];
    __shared__ float red_sum[8];
    #pragma unroll
    for (int o = 16; o; o >>= 1) m = fmaxf(m, __shfl_xor_sync(0xffffffffu, m, o));
    if ((t & 31) == 0) red_max[t >> 5] = m;
    __syncthreads();
    float rowmax = red_max[0];
    #pragma unroll
    for (int i = 1; i < 8; ++i) rowmax = fmaxf(rowmax, red_max[i]);

    float sum = 0.f;
    #pragma unroll
    for (int i = 0; i < 8; ++i) {
        vals[i] = __expf(vals[i] - rowmax);
        sum += vals[i];
    }
    #pragma unroll
    for (int o = 16; o; o >>= 1) sum += __shfl_xor_sync(0xffffffffu, sum, o);
    if ((t & 31) == 0) red_sum[t >> 5] = sum;
    __syncthreads();
    float total = 0.f;
    #pragma unroll
    for (int i = 0; i < 8; ++i) total += red_sum[i];

    const float inv = 1.0f / total;
    #pragma unroll
    for (int i = 0; i < 8; ++i) p[t + i * 256] = vals[i] * inv;
}

// ---------------------------------------------------------------------------
// AV: per (b,h): O[m, d] = sum_k P[m,k] * V[k,d]   (NN GEMM, N=HD=64)
// Writes directly back into [B,S,HID] layout for the output projection.
// ---------------------------------------------------------------------------
__global__ __launch_bounds__(256) void av_kernel(const float* __restrict__ P)
{
    __shared__ float As[16][68];   // P tile transposed: [k][m]
    __shared__ float Bs[16][68];   // V tile: [k][n]

    const int bh = blockIdx.z;
    const int b  = bh / NHc, h = bh % NHc;
    const float* Pp = P   + (size_t)bh * Sc * Sc;
    const float* V  = g_V + (size_t)bh * Sc * HDc;

    const int tid  = threadIdx.x;
    const int lrow = tid >> 2;           // 0..63 (m)
    const int lk   = (tid & 3) << 2;     // 0,4,8,12 (k)
    const int rowB = tid >> 4;           // 0..15 (k)
    const int colB = (tid & 15) << 2;    // 0..60 (n)
    const int m0   = blockIdx.x * 64;
    const int tm   = (tid >> 4) << 2;
    const int tn   = (tid & 15) << 2;

    float acc[4][4] = {};
    const float* Arow = Pp + (size_t)(m0 + lrow) * Sc + lk;

    for (int k0 = 0; k0 < Sc; k0 += 16) {
        float4 a = *(const float4*)(Arow + k0);
        float4 v4 = *(const float4*)(V + (size_t)(k0 + rowB) * HDc + colB);
        As[lk+0][lrow] = a.x; As[lk+1][lrow] = a.y;
        As[lk+2][lrow] = a.z; As[lk+3][lrow] = a.w;
        *(float4*)&Bs[rowB][colB] = v4;
        __syncthreads();
        #pragma unroll
        for (int k = 0; k < 16; ++k) {
            float4 av = *(const float4*)&As[k][tm];
            float4 bv = *(const float4*)&Bs[k][tn];
            float ar[4] = {av.x, av.y, av.z, av.w};
            float br[4] = {bv.x, bv.y, bv.z, bv.w};
            #pragma unroll
            for (int i = 0; i < 4; ++i)
                #pragma unroll
                for (int j = 0; j < 4; ++j)
                    acc[i][j] = fmaf(ar[i], br[j], acc[i][j]);
        }
        __syncthreads();
    }

    #pragma unroll
    for (int i = 0; i < 4; ++i) {
        int m = m0 + tm + i;
        #pragma unroll
        for (int j = 0; j < 4; ++j) {
            int n = tn + j;  // d within head
            g_O[((size_t)(b * Sc + m)) * HIDc + h * HDc + n] = acc[i][j];
        }
    }
}

// ---------------------------------------------------------------------------
extern "C" void kernel_launch(void* const* d_in, const int* in_sizes, int n_in,
                              void* d_out, int out_size)
{
    (void)in_sizes; (void)n_in; (void)out_size;
    const float* query = (const float*)d_in[0];
    const float* key   = (const float*)d_in[1];
    const float* value = (const float*)d_in[2];
    const int*   amask = (const int*)  d_in[3];
    const float* sim   = (const float*)d_in[4];
    const float* Wq    = (const float*)d_in[5];
    const float* bq    = (const float*)d_in[6];
    const float* Wk    = (const float*)d_in[7];
    const float* bk    = (const float*)d_in[8];
    const float* Wv    = (const float*)d_in[9];
    const float* bv    = (const float*)d_in[10];
    const float* Wo    = (const float*)d_in[11];
    const float* bo    = (const float*)d_in[12];
    const float* beta  = (const float*)d_in[13];

    float* out     = (float*)d_out;                          // [B,S,HID]
    float* weights = out + (size_t)Bc * Sc * HIDc;           // [B,NH,S,S]

    static float *Qp = nullptr, *Kp = nullptr, *Vp = nullptr, *Op = nullptr;
    if (!Qp) {
        cudaGetSymbolAddress((void**)&Qp, g_Q);
        cudaGetSymbolAddress((void**)&Kp, g_K);
        cudaGetSymbolAddress((void**)&Vp, g_V);
        cudaGetSymbolAddress((void**)&Op, g_O);
    }

    dim3 blk(256);
    // 1) Q/K/V projections (head-permuted outputs)
    dim3 gproj(BSc / 64, HIDc / 64);
    gemm_nt_kernel<true><<<gproj, blk>>>(query, Wq, bq, Qp, BSc, HIDc, HIDc);
    gemm_nt_kernel<true><<<gproj, blk>>>(key,   Wk, bk, Kp, BSc, HIDc, HIDc);
    gemm_nt_kernel<true><<<gproj, blk>>>(value, Wv, bv, Vp, BSc, HIDc, HIDc);

    // 2) Scores -> attention-weights region (unnormalized)
    dim3 gsc(Sc / 64, Sc / 64, BHc);
    scores_kernel<<<gsc, blk>>>(sim, amask, beta, weights);

    // 3) Softmax in place
    softmax_kernel<<<(unsigned)(BHc * Sc), blk>>>(weights);

    // 4) AV -> g_O in [B,S,HID] layout
    dim3 gav(Sc / 64, 1, BHc);
    av_kernel<<<gav, blk>>>(weights);

    // 5) Output projection
    gemm_nt_kernel<false><<<gproj, blk>>>(Op, Wo, bo, out, BSc, HIDc, HIDc);
}

// round 4
// speedup vs baseline: 1.5861x; 1.5861x over previous
#include <cuda_runtime.h>
#include <cuda_bf16.h>
#include <math.h>
#include <stdint.h>

#define Bc   2
#define Sc   2048
#define HIDc 1024
#define NHc  16
#define HDc  64
#define BSc  (Bc * Sc)
#define BHc  (Bc * NHc)

#define LD 24   // smem row stride in bf16 elems (16 data + 8 pad): bank map 12g+t conflict-free

// Scratch (device globals — no allocation allowed)
__device__ float g_Q[(size_t)BHc * Sc * HDc];    // [bh][s][d]
__device__ float g_K[(size_t)BHc * Sc * HDc];    // [bh][s][d]
__device__ float g_V[(size_t)BHc * Sc * HDc];    // [bh][d][s]  (transposed!)
__device__ float g_O[(size_t)Bc  * Sc * HIDc];   // [b][s][hid]
__device__ float g_part[(size_t)BHc * Sc * 16];  // per-row per-ktile partial exp sums
__device__ float g_inv [(size_t)BHc * Sc];       // 1 / rowsum(exp)

// ---------------------------------------------------------------------------
// helpers
// ---------------------------------------------------------------------------
__device__ __forceinline__ uint32_t ld32bf(const __nv_bfloat16* p) {
    return *reinterpret_cast<const uint32_t*>(p);
}
__device__ __forceinline__ uint32_t pack_bf16x2(float x0, float x1) {
    uint32_t r;
    asm("cvt.rn.bf16x2.f32 %0, %1, %2;" : "=r"(r) : "f"(x1), "f"(x0));
    return r;  // x0 -> low half, x1 -> high half
}
__device__ __forceinline__ void mma_bf16(float c[4], const uint32_t a[4], const uint32_t b[2]) {
    asm volatile(
        "mma.sync.aligned.m16n8k16.row.col.f32.bf16.bf16.f32 "
        "{%0,%1,%2,%3},{%4,%5,%6,%7},{%8,%9},{%0,%1,%2,%3};"
        : "+f"(c[0]), "+f"(c[1]), "+f"(c[2]), "+f"(c[3])
        : "r"(a[0]), "r"(a[1]), "r"(a[2]), "r"(a[3]), "r"(b[0]), "r"(b[1]));
}

// 8 fp32 -> bf16 hi (exact top-16-bits) + bf16 lo (residual), 16B store each
__device__ __forceinline__ void cvt_store8(const float v[8],
                                           __nv_bfloat16* hi, __nv_bfloat16* lo) {
    uint32_t h[4], l[4];
    #pragma unroll
    for (int i = 0; i < 4; ++i) {
        uint32_t u0 = __float_as_uint(v[2*i]);
        uint32_t u1 = __float_as_uint(v[2*i+1]);
        h[i] = (u0 >> 16) | (u1 & 0xFFFF0000u);
        float l0 = v[2*i]   - __uint_as_float(u0 & 0xFFFF0000u);
        float l1 = v[2*i+1] - __uint_as_float(u1 & 0xFFFF0000u);
        l[i] = pack_bf16x2(l0, l1);
    }
    uint4 hv = make_uint4(h[0], h[1], h[2], h[3]);
    uint4 lv = make_uint4(l[0], l[1], l[2], l[3]);
    *reinterpret_cast<uint4*>(hi) = hv;
    *reinterpret_cast<uint4*>(lo) = lv;
}
// 4 fp32 variant, 8B stores
__device__ __forceinline__ void cvt_store4(const float v[4],
                                           __nv_bfloat16* hi, __nv_bfloat16* lo) {
    uint32_t h[2], l[2];
    #pragma unroll
    for (int i = 0; i < 2; ++i) {
        uint32_t u0 = __float_as_uint(v[2*i]);
        uint32_t u1 = __float_as_uint(v[2*i+1]);
        h[i] = (u0 >> 16) | (u1 & 0xFFFF0000u);
        float l0 = v[2*i]   - __uint_as_float(u0 & 0xFFFF0000u);
        float l1 = v[2*i+1] - __uint_as_float(u1 & 0xFFFF0000u);
        l[i] = pack_bf16x2(l0, l1);
    }
    *reinterpret_cast<uint2*>(hi) = make_uint2(h[0], h[1]);
    *reinterpret_cast<uint2*>(lo) = make_uint2(l[0], l[1]);
}
__device__ __forceinline__ void gload8(const float* p, float r[8]) {
    float4 x = *reinterpret_cast<const float4*>(p);
    float4 y = *reinterpret_cast<const float4*>(p + 4);
    r[0]=x.x; r[1]=x.y; r[2]=x.z; r[3]=x.w; r[4]=y.x; r[5]=y.y; r[6]=y.z; r[7]=y.w;
}

// One BK=16 MMA step for a warp tile (MI x NJ of m16n8 tiles), bf16x3 split.
template<int MI, int NJ>
__device__ __forceinline__ void mma_tile(
    const __nv_bfloat16* Ah, const __nv_bfloat16* Al,
    const __nv_bfloat16* Bh, const __nv_bfloat16* Bl,
    int aRow0, int bCol0, int g, int t,
    float (&c)[MI][NJ][4])
{
    uint32_t ah[MI][4], al[MI][4], bh[NJ][2], bl[NJ][2];
    #pragma unroll
    for (int mi = 0; mi < MI; ++mi) {
        int r = aRow0 + mi * 16 + g;
        const __nv_bfloat16* p0 = Ah + r * LD + 2 * t;
        const __nv_bfloat16* p1 = p0 + 8 * LD;
        ah[mi][0] = ld32bf(p0);     ah[mi][1] = ld32bf(p1);
        ah[mi][2] = ld32bf(p0 + 8); ah[mi][3] = ld32bf(p1 + 8);
        const __nv_bfloat16* q0 = Al + r * LD + 2 * t;
        const __nv_bfloat16* q1 = q0 + 8 * LD;
        al[mi][0] = ld32bf(q0);     al[mi][1] = ld32bf(q1);
        al[mi][2] = ld32bf(q0 + 8); al[mi][3] = ld32bf(q1 + 8);
    }
    #pragma unroll
    for (int nj = 0; nj < NJ; ++nj) {
        int n = bCol0 + nj * 8 + g;
        const __nv_bfloat16* p = Bh + n * LD + 2 * t;
        bh[nj][0] = ld32bf(p); bh[nj][1] = ld32bf(p + 8);
        const __nv_bfloat16* q = Bl + n * LD + 2 * t;
        bl[nj][0] = ld32bf(q); bl[nj][1] = ld32bf(q + 8);
    }
    #pragma unroll
    for (int mi = 0; mi < MI; ++mi)
        #pragma unroll
        for (int nj = 0; nj < NJ; ++nj) {
            mma_bf16(c[mi][nj], ah[mi], bh[nj]);
            mma_bf16(c[mi][nj], ah[mi], bl[nj]);
            mma_bf16(c[mi][nj], al[mi], bh[nj]);
        }
}

// ---------------------------------------------------------------------------
// NT GEMM: C[M,N] = A[M,K] @ W[N,K]^T + bias, 128x128 tile, bf16x3, dbl-buffered
// MODE 0: plain [M,N]; 1: Q/K permute -> [bh][s][d]; 2: V permute -> [bh][d][s]
// ---------------------------------------------------------------------------
template<int MODE>
__global__ __launch_bounds__(256, 1) void gemm_bf3_kernel(
    const float* __restrict__ A, const float* __restrict__ W,
    const float* __restrict__ bias, float* __restrict__ C,
    int M, int N, int K)
{
    __shared__ __nv_bfloat16 sA[2][2][128 * LD];
    __shared__ __nv_bfloat16 sB[2][2][128 * LD];

    const int tid = threadIdx.x;
    const int wid = tid >> 5, lane = tid & 31;
    const int wm = wid >> 2, wn = wid & 3;      // 2 x 4 warps, warp tile 64x32
    const int g = lane >> 2, t = lane & 3;
    const int m0 = blockIdx.y * 128, n0 = blockIdx.x * 128;

    const int lrow = tid >> 1, lcol = (tid & 1) * 8;
    const float* Ap = A + (size_t)(m0 + lrow) * K + lcol;
    const float* Bp = W + (size_t)(n0 + lrow) * K + lcol;

    float c[4][4][4];
    #pragma unroll
    for (int i = 0; i < 4; ++i)
        #pragma unroll
        for (int j = 0; j < 4; ++j)
            #pragma unroll
            for (int k = 0; k < 4; ++k) c[i][j][k] = 0.f;

    float ra[8], rb[8];
    const int KT = K >> 4;

    gload8(Ap, ra);
    gload8(Bp, rb);
    cvt_store8(ra, &sA[0][0][lrow*LD + lcol], &sA[0][1][lrow*LD + lcol]);
    cvt_store8(rb, &sB[0][0][lrow*LD + lcol], &sB[0][1][lrow*LD + lcol]);
    __syncthreads();

    for (int kt = 0; kt < KT; ++kt) {
        int cur = kt & 1;
        if (kt + 1 < KT) {
            gload8(Ap + (kt + 1) * 16, ra);
            gload8(Bp + (kt + 1) * 16, rb);
        }
        mma_tile<4,4>(sA[cur][0], sA[cur][1], sB[cur][0], sB[cur][1],
                      wm * 64, wn * 32, g, t, c);
        if (kt + 1 < KT) {
            int nxt = cur ^ 1;
            cvt_store8(ra, &sA[nxt][0][lrow*LD + lcol], &sA[nxt][1][lrow*LD + lcol]);
            cvt_store8(rb, &sB[nxt][0][lrow*LD + lcol], &sB[nxt][1][lrow*LD + lcol]);
        }
        __syncthreads();
    }

    #pragma unroll
    for (int nj = 0; nj < 4; ++nj) {
        int n = n0 + wn * 32 + nj * 8 + 2 * t;
        float b0 = bias[n], b1 = bias[n + 1];
        #pragma unroll
        for (int mi = 0; mi < 4; ++mi) {
            int r = m0 + wm * 64 + mi * 16 + g;
            #pragma unroll
            for (int half = 0; half < 2; ++half) {
                int rr = r + half * 8;
                float v0 = c[mi][nj][2*half]     + b0;
                float v1 = c[mi][nj][2*half + 1] + b1;
                if (MODE == 0) {
                    *reinterpret_cast<float2*>(&C[(size_t)rr * N + n]) = make_float2(v0, v1);
                } else {
                    int b = rr / Sc, s = rr % Sc;
                    int h = n / HDc, d = n % HDc;
                    if (MODE == 1) {
                        *reinterpret_cast<float2*>(
                            &C[(((size_t)(b * NHc + h)) * Sc + s) * HDc + d]) = make_float2(v0, v1);
                    } else {
                        C[(((size_t)(b * NHc + h)) * HDc + d)     * Sc + s] = v0;
                        C[(((size_t)(b * NHc + h)) * HDc + d + 1) * Sc + s] = v1;
                    }
                }
            }
        }
    }
}

// ---------------------------------------------------------------------------
// Scores: e = exp(QK/8 + beta*sim, masked), write e to weights region,
// emit per-(row, ktile) partial sums. 128x128 tile, bf16x3, K=64.
// ---------------------------------------------------------------------------
__global__ __launch_bounds__(256, 1) void scores_kernel(
    const float* __restrict__ sim, const int* __restrict__ mask,
    const float* __restrict__ beta_p, float* __restrict__ Wt)
{
    __shared__ __nv_bfloat16 sA[2][128 * LD];   // [part][...], single-buffered
    __shared__ __nv_bfloat16 sB[2][128 * LD];
    __shared__ float spart[128][4];

    const int tid = threadIdx.x;
    const int wid = tid >> 5, lane = tid & 31;
    const int wm = wid >> 2, wn = wid & 3;
    const int g = lane >> 2, t = lane & 3;
    const int bh = blockIdx.z, b = bh >> 4;
    const int m0 = blockIdx.y * 128, n0 = blockIdx.x * 128;

    const int lrow = tid >> 1, lcol = (tid & 1) * 8;
    const float* Ap = g_Q + (size_t)bh * Sc * HDc + (size_t)(m0 + lrow) * HDc + lcol;
    const float* Bp = g_K + (size_t)bh * Sc * HDc + (size_t)(n0 + lrow) * HDc + lcol;

    float c[4][4][4];
    #pragma unroll
    for (int i = 0; i < 4; ++i)
        #pragma unroll
        for (int j = 0; j < 4; ++j)
            #pragma unroll
            for (int k = 0; k < 4; ++k) c[i][j][k] = 0.f;

    #pragma unroll
    for (int kt = 0; kt < HDc / 16; ++kt) {
        float ra[8], rb[8];
        gload8(Ap + kt * 16, ra);
        gload8(Bp + kt * 16, rb);
        __syncthreads();   // previous compute done before overwrite
        cvt_store8(ra, &sA[0][lrow*LD + lcol], &sA[1][lrow*LD + lcol]);
        cvt_store8(rb, &sB[0][lrow*LD + lcol], &sB[1][lrow*LD + lcol]);
        __syncthreads();
        mma_tile<4,4>(sA[0], sA[1], sB[0], sB[1], wm * 64, wn * 32, g, t, c);
    }

    const float beta = *beta_p;
    float rsum[4][2];
    #pragma unroll
    for (int i = 0; i < 4; ++i) { rsum[i][0] = 0.f; rsum[i][1] = 0.f; }

    #pragma unroll
    for (int mi = 0; mi < 4; ++mi) {
        int q = m0 + wm * 64 + mi * 16 + g;
        #pragma unroll
        for (int half = 0; half < 2; ++half) {
            int qq = q + half * 8;
            #pragma unroll
            for (int nj = 0; nj < 4; ++nj) {
                int kc = n0 + wn * 32 + nj * 8 + 2 * t;
                float2 sv = *reinterpret_cast<const float2*>(
                    &sim[((size_t)b * Sc + qq) * Sc + kc]);
                int2 mk = *reinterpret_cast<const int2*>(&mask[b * Sc + kc]);
                float s0 = c[mi][nj][2*half]     * 0.125f + beta * sv.x;
                float s1 = c[mi][nj][2*half + 1] * 0.125f + beta * sv.y;
                if (mk.x == 0) s0 = -1e30f;
                if (mk.y == 0) s1 = -1e30f;
                float e0 = __expf(s0), e1 = __expf(s1);
                *reinterpret_cast<float2*>(
                    &Wt[((size_t)bh * Sc + qq) * Sc + kc]) = make_float2(e0, e1);
                rsum[mi][half] += e0 + e1;
            }
        }
    }
    #pragma unroll
    for (int mi = 0; mi < 4; ++mi)
        #pragma unroll
        for (int half = 0; half < 2; ++half) {
            float v = rsum[mi][half];
            v += __shfl_xor_sync(0xffffffffu, v, 1);
            v += __shfl_xor_sync(0xffffffffu, v, 2);
            if (t == 0) spart[wm * 64 + mi * 16 + half * 8 + g][wn] = v;
        }
    __syncthreads();
    if (tid < 128) {
        float s = spart[tid][0] + spart[tid][1] + spart[tid][2] + spart[tid][3];
        g_part[((size_t)bh * Sc + m0 + tid) * 16 + blockIdx.x] = s;
    }
}

// ---------------------------------------------------------------------------
// inv rowsum: deterministic sum of 16 partials per row
// ---------------------------------------------------------------------------
__global__ __launch_bounds__(256) void inv_kernel()
{
    int i = blockIdx.x * 256 + threadIdx.x;   // 65536 rows
    const float4* p = reinterpret_cast<const float4*>(g_part + (size_t)i * 16);
    float4 a = p[0], bb = p[1], cc = p[2], d = p[3];
    float s = ((a.x + a.y) + (a.z + a.w)) + ((bb.x + bb.y) + (bb.z + bb.w))
            + ((cc.x + cc.y) + (cc.z + cc.w)) + ((d.x + d.y) + (d.z + d.w));
    g_inv[i] = 1.0f / s;
}

// ---------------------------------------------------------------------------
// AV: normalize e -> p in-place (writes attention_weights output), accumulate
// O = P @ V^T (V stored [d][s]). 128x64 tile, warps 4x2 (warp 32x32), K=2048.
// ---------------------------------------------------------------------------
__global__ __launch_bounds__(256, 1) void av_kernel(float* __restrict__ Wt)
{
    __shared__ __nv_bfloat16 sA[2][2][128 * LD];
    __shared__ __nv_bfloat16 sB[2][2][64 * LD];

    const int tid = threadIdx.x;
    const int wid = tid >> 5, lane = tid & 31;
    const int wm = wid >> 1, wn = wid & 1;      // 4 x 2 warps, warp tile 32x32
    const int g = lane >> 2, t = lane & 3;
    const int bh = blockIdx.z, b = bh >> 4, h = bh & 15;
    const int m0 = blockIdx.x * 128;

    const int lrowA = tid >> 1, lcolA = (tid & 1) * 8;
    float* ApE = Wt + (size_t)bh * Sc * Sc + (size_t)(m0 + lrowA) * Sc + lcolA;
    const float inv = g_inv[(size_t)bh * Sc + m0 + lrowA];

    const int lrowB = tid >> 2, lcolB = (tid & 3) * 4;
    const float* Bp = g_V + (size_t)bh * HDc * Sc + (size_t)lrowB * Sc + lcolB;

    float c[2][4][4];
    #pragma unroll
    for (int i = 0; i < 2; ++i)
        #pragma unroll
        for (int j = 0; j < 4; ++j)
            #pragma unroll
            for (int k = 0; k < 4; ++k) c[i][j][k] = 0.f;

    float ra[8], rb[4];
    const int KT = Sc / 16;  // 128

    // prologue: load, normalize+writeback, stage
    {
        float4 x = *reinterpret_cast<const float4*>(ApE);
        float4 y = *reinterpret_cast<const float4*>(ApE + 4);
        x.x*=inv; x.y*=inv; x.z*=inv; x.w*=inv;
        y.x*=inv; y.y*=inv; y.z*=inv; y.w*=inv;
        *reinterpret_cast<float4*>(ApE)     = x;
        *reinterpret_cast<float4*>(ApE + 4) = y;
        ra[0]=x.x; ra[1]=x.y; ra[2]=x.z; ra[3]=x.w; ra[4]=y.x; ra[5]=y.y; ra[6]=y.z; ra[7]=y.w;
        float4 v = *reinterpret_cast<const float4*>(Bp);
        rb[0]=v.x; rb[1]=v.y; rb[2]=v.z; rb[3]=v.w;
        cvt_store8(ra, &sA[0][0][lrowA*LD + lcolA], &sA[0][1][lrowA*LD + lcolA]);
        cvt_store4(rb, &sB[0][0][lrowB*LD + lcolB], &sB[0][1][lrowB*LD + lcolB]);
    }
    __syncthreads();

    for (int kt = 0; kt < KT; ++kt) {
        int cur = kt & 1;
        if (kt + 1 < KT) {
            float* pe = ApE + (kt + 1) * 16;
            float4 x = *reinterpret_cast<const float4*>(pe);
            float4 y = *reinterpret_cast<const float4*>(pe + 4);
            x.x*=inv; x.y*=inv; x.z*=inv; x.w*=inv;
            y.x*=inv; y.y*=inv; y.z*=inv; y.w*=inv;
            *reinterpret_cast<float4*>(pe)     = x;
            *reinterpret_cast<float4*>(pe + 4) = y;
            ra[0]=x.x; ra[1]=x.y; ra[2]=x.z; ra[3]=x.w; ra[4]=y.x; ra[5]=y.y; ra[6]=y.z; ra[7]=y.w;
            float4 v = *reinterpret_cast<const float4*>(Bp + (kt + 1) * 16);
            rb[0]=v.x; rb[1]=v.y; rb[2]=v.z; rb[3]=v.w;
        }
        mma_tile<2,4>(sA[cur][0], sA[cur][1], sB[cur][0], sB[cur][1],
                      wm * 32, wn * 32, g, t, c);
        if (kt + 1 < KT) {
            int nxt = cur ^ 1;
            cvt_store8(ra, &sA[nxt][0][lrowA*LD + lcolA], &sA[nxt][1][lrowA*LD + lcolA]);
            cvt_store4(rb, &sB[nxt][0][lrowB*LD + lcolB], &sB[nxt][1][lrowB*LD + lcolB]);
        }
        __syncthreads();
    }

    #pragma unroll
    for (int mi = 0; mi < 2; ++mi)
        #pragma unroll
        for (int nj = 0; nj < 4; ++nj)
            #pragma unroll
            for (int half = 0; half < 2; ++half) {
                int q = m0 + wm * 32 + mi * 16 + half * 8 + g;
                int d = wn * 32 + nj * 8 + 2 * t;
                float2 vv = make_float2(c[mi][nj][2*half], c[mi][nj][2*half + 1]);
                *reinterpret_cast<float2*>(
                    &g_O[((size_t)(b * Sc) + q) * HIDc + h * HDc + d]) = vv;
            }
}

// ---------------------------------------------------------------------------
extern "C" void kernel_launch(void* const* d_in, const int* in_sizes, int n_in,
                              void* d_out, int out_size)
{
    (void)in_sizes; (void)n_in; (void)out_size;
    const float* query = (const float*)d_in[0];
    const float* key   = (const float*)d_in[1];
    const float* value = (const float*)d_in[2];
    const int*   amask = (const int*)  d_in[3];
    const float* sim   = (const float*)d_in[4];
    const float* Wq    = (const float*)d_in[5];
    const float* bq    = (const float*)d_in[6];
    const float* Wk    = (const float*)d_in[7];
    const float* bk    = (const float*)d_in[8];
    const float* Wv    = (const float*)d_in[9];
    const float* bv    = (const float*)d_in[10];
    const float* Wo    = (const float*)d_in[11];
    const float* bo    = (const float*)d_in[12];
    const float* beta  = (const float*)d_in[13];

    float* out     = (float*)d_out;                      // [B,S,HID]
    float* weights = out + (size_t)Bc * Sc * HIDc;       // [B,NH,S,S]

    static float *Qp = nullptr, *Kp = nullptr, *Vp = nullptr, *Op = nullptr;
    if (!Qp) {
        cudaGetSymbolAddress((void**)&Qp, g_Q);
        cudaGetSymbolAddress((void**)&Kp, g_K);
        cudaGetSymbolAddress((void**)&Vp, g_V);
        cudaGetSymbolAddress((void**)&Op, g_O);
    }

    dim3 blk(256);
    dim3 gproj(HIDc / 128, BSc / 128);   // (8, 32)

    gemm_bf3_kernel<1><<<gproj, blk>>>(query, Wq, bq, Qp, BSc, HIDc, HIDc);
    gemm_bf3_kernel<1><<<gproj, blk>>>(key,   Wk, bk, Kp, BSc, HIDc, HIDc);
    gemm_bf3_kernel<2><<<gproj, blk>>>(value, Wv, bv, Vp, BSc, HIDc, HIDc);

    dim3 gsc(Sc / 128, Sc / 128, BHc);   // (16, 16, 32)
    scores_kernel<<<gsc, blk>>>(sim, amask, beta, weights);

    inv_kernel<<<(BHc * Sc) / 256, blk>>>();

    dim3 gav(Sc / 128, 1, BHc);          // (16, 1, 32)
    av_kernel<<<gav, blk>>>(weights);

    gemm_bf3_kernel<0><<<gproj, blk>>>(Op, Wo, bo, out, BSc, HIDc, HIDc);
}

// round 6
// speedup vs baseline: 1.6657x; 1.0502x over previous
#include <cuda_runtime.h>
#include <cuda_bf16.h>
#include <math.h>
#include <stdint.h>

#define Bc   2
#define Sc   2048
#define HIDc 1024
#define NHc  16
#define HDc  64
#define BSc  (Bc * Sc)
#define BHc  (Bc * NHc)

#define LDg 24   // smem bf16 row stride for BK=16 tiles (16 data + 8 pad)
#define LDs 72   // smem bf16 row stride for scores (64 data + 8 pad)

// Scratch (device globals — no allocation allowed)
__device__ float g_Q[(size_t)BHc * Sc * HDc];    // [bh][s][d]
__device__ float g_K[(size_t)BHc * Sc * HDc];    // [bh][s][d]
__device__ float g_V[(size_t)BHc * Sc * HDc];    // [bh][d][s]  (transposed)
__device__ float g_O[(size_t)Bc  * Sc * HIDc];   // [b][s][hid]
__device__ float g_part[(size_t)BHc * Sc * 16];  // per-row per-ntile partial exp sums
__device__ float g_inv [(size_t)BHc * Sc];       // 1 / rowsum(exp)

// ---------------------------------------------------------------------------
// helpers
// ---------------------------------------------------------------------------
__device__ __forceinline__ uint32_t ld32bf(const __nv_bfloat16* p) {
    return *reinterpret_cast<const uint32_t*>(p);
}
__device__ __forceinline__ uint32_t pack_bf16x2(float x0, float x1) {
    uint32_t r;
    asm("cvt.rn.bf16x2.f32 %0, %1, %2;" : "=r"(r) : "f"(x1), "f"(x0));
    return r;
}
__device__ __forceinline__ void mma_bf16(float c[4], const uint32_t a[4], const uint32_t b[2]) {
    asm volatile(
        "mma.sync.aligned.m16n8k16.row.col.f32.bf16.bf16.f32 "
        "{%0,%1,%2,%3},{%4,%5,%6,%7},{%8,%9},{%0,%1,%2,%3};"
        : "+f"(c[0]), "+f"(c[1]), "+f"(c[2]), "+f"(c[3])
        : "r"(a[0]), "r"(a[1]), "r"(a[2]), "r"(a[3]), "r"(b[0]), "r"(b[1]));
}

// fp32 -> bf16 hi (exact top-16 bits) + bf16 lo (residual)
__device__ __forceinline__ void cvt_store8(const float v[8],
                                           __nv_bfloat16* hi, __nv_bfloat16* lo) {
    uint32_t h[4], l[4];
    #pragma unroll
    for (int i = 0; i < 4; ++i) {
        uint32_t u0 = __float_as_uint(v[2*i]);
        uint32_t u1 = __float_as_uint(v[2*i+1]);
        h[i] = (u0 >> 16) | (u1 & 0xFFFF0000u);
        float l0 = v[2*i]   - __uint_as_float(u0 & 0xFFFF0000u);
        float l1 = v[2*i+1] - __uint_as_float(u1 & 0xFFFF0000u);
        l[i] = pack_bf16x2(l0, l1);
    }
    *reinterpret_cast<uint4*>(hi) = make_uint4(h[0], h[1], h[2], h[3]);
    *reinterpret_cast<uint4*>(lo) = make_uint4(l[0], l[1], l[2], l[3]);
}
__device__ __forceinline__ void cvt_store4(const float v[4],
                                           __nv_bfloat16* hi, __nv_bfloat16* lo) {
    uint32_t h[2], l[2];
    #pragma unroll
    for (int i = 0; i < 2; ++i) {
        uint32_t u0 = __float_as_uint(v[2*i]);
        uint32_t u1 = __float_as_uint(v[2*i+1]);
        h[i] = (u0 >> 16) | (u1 & 0xFFFF0000u);
        float l0 = v[2*i]   - __uint_as_float(u0 & 0xFFFF0000u);
        float l1 = v[2*i+1] - __uint_as_float(u1 & 0xFFFF0000u);
        l[i] = pack_bf16x2(l0, l1);
    }
    *reinterpret_cast<uint2*>(hi) = make_uint2(h[0], h[1]);
    *reinterpret_cast<uint2*>(lo) = make_uint2(l[0], l[1]);
}
__device__ __forceinline__ void cvt_store2(const float v[2],
                                           __nv_bfloat16* hi, __nv_bfloat16* lo) {
    uint32_t u0 = __float_as_uint(v[0]);
    uint32_t u1 = __float_as_uint(v[1]);
    uint32_t h = (u0 >> 16) | (u1 & 0xFFFF0000u);
    float l0 = v[0] - __uint_as_float(u0 & 0xFFFF0000u);
    float l1 = v[1] - __uint_as_float(u1 & 0xFFFF0000u);
    *reinterpret_cast<uint32_t*>(hi) = h;
    *reinterpret_cast<uint32_t*>(lo) = pack_bf16x2(l0, l1);
}
__device__ __forceinline__ void gload8(const float* p, float r[8]) {
    float4 x = *reinterpret_cast<const float4*>(p);
    float4 y = *reinterpret_cast<const float4*>(p + 4);
    r[0]=x.x; r[1]=x.y; r[2]=x.z; r[3]=x.w; r[4]=y.x; r[5]=y.y; r[6]=y.z; r[7]=y.w;
}
__device__ __forceinline__ void gload4(const float* p, float r[4]) {
    float4 x = *reinterpret_cast<const float4*>(p);
    r[0]=x.x; r[1]=x.y; r[2]=x.z; r[3]=x.w;
}

// One BK=16 MMA step for a warp tile (MI x NJ m16n8 tiles), bf16x3 split.
template<int MI, int NJ, int LDm>
__device__ __forceinline__ void mma_tile(
    const __nv_bfloat16* Ah, const __nv_bfloat16* Al,
    const __nv_bfloat16* Bh, const __nv_bfloat16* Bl,
    int aRow0, int bCol0, int g, int t,
    float (&c)[MI][NJ][4])
{
    uint32_t ah[MI][4], al[MI][4], bh[NJ][2], bl[NJ][2];
    #pragma unroll
    for (int mi = 0; mi < MI; ++mi) {
        int r = aRow0 + mi * 16 + g;
        const __nv_bfloat16* p0 = Ah + r * LDm + 2 * t;
        const __nv_bfloat16* p1 = p0 + 8 * LDm;
        ah[mi][0] = ld32bf(p0);     ah[mi][1] = ld32bf(p1);
        ah[mi][2] = ld32bf(p0 + 8); ah[mi][3] = ld32bf(p1 + 8);
        const __nv_bfloat16* q0 = Al + r * LDm + 2 * t;
        const __nv_bfloat16* q1 = q0 + 8 * LDm;
        al[mi][0] = ld32bf(q0);     al[mi][1] = ld32bf(q1);
        al[mi][2] = ld32bf(q0 + 8); al[mi][3] = ld32bf(q1 + 8);
    }
    #pragma unroll
    for (int nj = 0; nj < NJ; ++nj) {
        int n = bCol0 + nj * 8 + g;
        const __nv_bfloat16* p = Bh + n * LDm + 2 * t;
        bh[nj][0] = ld32bf(p); bh[nj][1] = ld32bf(p + 8);
        const __nv_bfloat16* q = Bl + n * LDm + 2 * t;
        bl[nj][0] = ld32bf(q); bl[nj][1] = ld32bf(q + 8);
    }
    #pragma unroll
    for (int mi = 0; mi < MI; ++mi)
        #pragma unroll
        for (int nj = 0; nj < NJ; ++nj) {
            mma_bf16(c[mi][nj], ah[mi], bh[nj]);
            mma_bf16(c[mi][nj], ah[mi], bl[nj]);
            mma_bf16(c[mi][nj], al[mi], bh[nj]);
        }
}

// ---------------------------------------------------------------------------
// NT GEMM: C[M,N] = A[M,K] @ W[N,K]^T + bias. 128x128 tile, 512 thr, warp 32x32.
// MODE 0: plain [M,N]; 1: Q/K permute -> [bh][s][d]; 2: V permute -> [bh][d][s]
// Static smem = 48KB exactly.
// ---------------------------------------------------------------------------
template<int MODE>
__global__ __launch_bounds__(512, 1) void gemm_bf3_kernel(
    const float* __restrict__ A, const float* __restrict__ W,
    const float* __restrict__ bias, float* __restrict__ C,
    int M, int N, int K)
{
    __shared__ __nv_bfloat16 sA[2][2][128 * LDg];
    __shared__ __nv_bfloat16 sB[2][2][128 * LDg];

    const int tid = threadIdx.x;
    const int wid = tid >> 5, lane = tid & 31;
    const int wm = wid >> 2, wn = wid & 3;      // 4x4 warps, warp tile 32x32
    const int g = lane >> 2, t = lane & 3;
    const int m0 = blockIdx.y * 128, n0 = blockIdx.x * 128;

    const int lrow = tid >> 2, lcol = (tid & 3) * 4;
    const float* Ap = A + (size_t)(m0 + lrow) * K + lcol;
    const float* Bp = W + (size_t)(n0 + lrow) * K + lcol;

    float c[2][4][4];
    #pragma unroll
    for (int i = 0; i < 2; ++i)
        #pragma unroll
        for (int j = 0; j < 4; ++j)
            #pragma unroll
            for (int k = 0; k < 4; ++k) c[i][j][k] = 0.f;

    float ra[4], rb[4];
    const int KT = K >> 4;

    gload4(Ap, ra);
    gload4(Bp, rb);
    cvt_store4(ra, &sA[0][0][lrow*LDg + lcol], &sA[0][1][lrow*LDg + lcol]);
    cvt_store4(rb, &sB[0][0][lrow*LDg + lcol], &sB[0][1][lrow*LDg + lcol]);
    __syncthreads();

    for (int kt = 0; kt < KT; ++kt) {
        int cur = kt & 1;
        if (kt + 1 < KT) {
            gload4(Ap + (kt + 1) * 16, ra);
            gload4(Bp + (kt + 1) * 16, rb);
        }
        mma_tile<2,4,LDg>(sA[cur][0], sA[cur][1], sB[cur][0], sB[cur][1],
                          wm * 32, wn * 32, g, t, c);
        if (kt + 1 < KT) {
            int nxt = cur ^ 1;
            cvt_store4(ra, &sA[nxt][0][lrow*LDg + lcol], &sA[nxt][1][lrow*LDg + lcol]);
            cvt_store4(rb, &sB[nxt][0][lrow*LDg + lcol], &sB[nxt][1][lrow*LDg + lcol]);
        }
        __syncthreads();
    }

    #pragma unroll
    for (int nj = 0; nj < 4; ++nj) {
        int n = n0 + wn * 32 + nj * 8 + 2 * t;
        float b0 = bias[n], b1 = bias[n + 1];
        #pragma unroll
        for (int mi = 0; mi < 2; ++mi) {
            #pragma unroll
            for (int half = 0; half < 2; ++half) {
                int rr = m0 + wm * 32 + mi * 16 + half * 8 + g;
                float v0 = c[mi][nj][2*half]     + b0;
                float v1 = c[mi][nj][2*half + 1] + b1;
                if (MODE == 0) {
                    *reinterpret_cast<float2*>(&C[(size_t)rr * N + n]) = make_float2(v0, v1);
                } else {
                    int b = rr / Sc, s = rr % Sc;
                    int h = n / HDc, d = n % HDc;
                    if (MODE == 1) {
                        *reinterpret_cast<float2*>(
                            &C[(((size_t)(b * NHc + h)) * Sc + s) * HDc + d]) = make_float2(v0, v1);
                    } else {
                        C[(((size_t)(b * NHc + h)) * HDc + d)     * Sc + s] = v0;
                        C[(((size_t)(b * NHc + h)) * HDc + d + 1) * Sc + s] = v1;
                    }
                }
            }
        }
    }
}

// ---------------------------------------------------------------------------
// Scores: e = exp(QK/8 + beta*sim, masked) -> weights region + row partials.
// 128x128 tile, 512 threads, full K=64 staged once (LDs=72), dynamic smem 72KB.
// ---------------------------------------------------------------------------
__global__ __launch_bounds__(512, 1) void scores_kernel(
    const float* __restrict__ sim, const int* __restrict__ mask,
    const float* __restrict__ beta_p, float* __restrict__ Wt)
{
    extern __shared__ __nv_bfloat16 dsm[];
    __nv_bfloat16* sAh = dsm;                    // 128*LDs
    __nv_bfloat16* sAl = sAh + 128 * LDs;
    __nv_bfloat16* sBh = sAl + 128 * LDs;
    __nv_bfloat16* sBl = sBh + 128 * LDs;
    __shared__ float spart[128][4];

    const int tid = threadIdx.x;
    const int wid = tid >> 5, lane = tid & 31;
    const int wm = wid >> 2, wn = wid & 3;
    const int g = lane >> 2, t = lane & 3;
    const int bh = blockIdx.z, b = bh >> 4;
    const int m0 = blockIdx.y * 128, n0 = blockIdx.x * 128;

    // stage full 128x64 Q and K tiles (hi+lo)
    const int lrow = tid >> 2, lcol = (tid & 3) * 16;
    {
        const float* Ap = g_Q + (size_t)bh * Sc * HDc + (size_t)(m0 + lrow) * HDc + lcol;
        const float* Bp = g_K + (size_t)bh * Sc * HDc + (size_t)(n0 + lrow) * HDc + lcol;
        float r0[8], r1[8];
        gload8(Ap, r0); gload8(Ap + 8, r1);
        cvt_store8(r0, &sAh[lrow*LDs + lcol],     &sAl[lrow*LDs + lcol]);
        cvt_store8(r1, &sAh[lrow*LDs + lcol + 8], &sAl[lrow*LDs + lcol + 8]);
        gload8(Bp, r0); gload8(Bp + 8, r1);
        cvt_store8(r0, &sBh[lrow*LDs + lcol],     &sBl[lrow*LDs + lcol]);
        cvt_store8(r1, &sBh[lrow*LDs + lcol + 8], &sBl[lrow*LDs + lcol + 8]);
    }
    __syncthreads();

    float c[2][4][4];
    #pragma unroll
    for (int i = 0; i < 2; ++i)
        #pragma unroll
        for (int j = 0; j < 4; ++j)
            #pragma unroll
            for (int k = 0; k < 4; ++k) c[i][j][k] = 0.f;

    #pragma unroll
    for (int kt = 0; kt < HDc / 16; ++kt) {
        mma_tile<2,4,LDs>(sAh + kt*16, sAl + kt*16, sBh + kt*16, sBl + kt*16,
                          wm * 32, wn * 32, g, t, c);
    }

    const float beta = *beta_p;
    float rsum[2][2];
    rsum[0][0] = rsum[0][1] = rsum[1][0] = rsum[1][1] = 0.f;

    #pragma unroll
    for (int mi = 0; mi < 2; ++mi) {
        #pragma unroll
        for (int half = 0; half < 2; ++half) {
            int qq = m0 + wm * 32 + mi * 16 + half * 8 + g;
            #pragma unroll
            for (int nj = 0; nj < 4; ++nj) {
                int kc = n0 + wn * 32 + nj * 8 + 2 * t;
                float2 sv = *reinterpret_cast<const float2*>(
                    &sim[((size_t)b * Sc + qq) * Sc + kc]);
                int2 mk = *reinterpret_cast<const int2*>(&mask[b * Sc + kc]);
                float s0 = c[mi][nj][2*half]     * 0.125f + beta * sv.x;
                float s1 = c[mi][nj][2*half + 1] * 0.125f + beta * sv.y;
                if (mk.x == 0) s0 = -1e30f;
                if (mk.y == 0) s1 = -1e30f;
                float e0 = __expf(s0), e1 = __expf(s1);
                *reinterpret_cast<float2*>(
                    &Wt[((size_t)bh * Sc + qq) * Sc + kc]) = make_float2(e0, e1);
                rsum[mi][half] += e0 + e1;
            }
        }
    }
    #pragma unroll
    for (int mi = 0; mi < 2; ++mi)
        #pragma unroll
        for (int half = 0; half < 2; ++half) {
            float v = rsum[mi][half];
            v += __shfl_xor_sync(0xffffffffu, v, 1);
            v += __shfl_xor_sync(0xffffffffu, v, 2);
            if (t == 0) spart[wm * 32 + mi * 16 + half * 8 + g][wn] = v;
        }
    __syncthreads();
    if (tid < 128) {
        float s = spart[tid][0] + spart[tid][1] + spart[tid][2] + spart[tid][3];
        g_part[((size_t)bh * Sc + m0 + tid) * 16 + blockIdx.x] = s;
    }
}

// ---------------------------------------------------------------------------
// inv rowsum: deterministic sum of 16 partials per row
// ---------------------------------------------------------------------------
__global__ __launch_bounds__(256) void inv_kernel()
{
    int i = blockIdx.x * 256 + threadIdx.x;
    const float4* p = reinterpret_cast<const float4*>(g_part + (size_t)i * 16);
    float4 a = p[0], bb = p[1], cc = p[2], d = p[3];
    float s = ((a.x + a.y) + (a.z + a.w)) + ((bb.x + bb.y) + (bb.z + bb.w))
            + ((cc.x + cc.y) + (cc.z + cc.w)) + ((d.x + d.y) + (d.z + d.w));
    g_inv[i] = 1.0f / s;
}

// ---------------------------------------------------------------------------
// AV: normalize e -> p in-place (final attention_weights), O = P @ V^T.
// 256x64 tile, 512 threads, warp grid 8x2 (warp 32x32), K=2048 dbl-buffered.
// Dynamic smem 60KB.
// ---------------------------------------------------------------------------
__global__ __launch_bounds__(512, 1) void av_kernel(float* __restrict__ Wt)
{
    extern __shared__ __nv_bfloat16 dsm[];
    __nv_bfloat16* sA = dsm;                           // [2 buf][2 plane][256*LDg]
    __nv_bfloat16* sB = dsm + 2 * 2 * 256 * LDg;       // [2 buf][2 plane][64*LDg]
    #define SA(buf, pl) (sA + ((buf) * 2 + (pl)) * 256 * LDg)
    #define SB(buf, pl) (sB + ((buf) * 2 + (pl)) * 64 * LDg)

    const int tid = threadIdx.x;
    const int wid = tid >> 5, lane = tid & 31;
    const int wm = wid >> 1, wn = wid & 1;      // 8x2 warps
    const int g = lane >> 2, t = lane & 3;
    const int bh = blockIdx.z, b = bh >> 4, h = bh & 15;
    const int m0 = blockIdx.x * 256;

    const int lrowA = tid >> 1, lcolA = (tid & 1) * 8;
    float* ApE = Wt + (size_t)bh * Sc * Sc + (size_t)(m0 + lrowA) * Sc + lcolA;
    const float inv = g_inv[(size_t)bh * Sc + m0 + lrowA];

    const int lrowB = tid >> 3, lcolB = (tid & 7) * 2;
    const float* Bp = g_V + (size_t)bh * HDc * Sc + (size_t)lrowB * Sc + lcolB;

    float c[2][4][4];
    #pragma unroll
    for (int i = 0; i < 2; ++i)
        #pragma unroll
        for (int j = 0; j < 4; ++j)
            #pragma unroll
            for (int k = 0; k < 4; ++k) c[i][j][k] = 0.f;

    float ra[8], rb[2];
    const int KT = Sc / 16;  // 128

    {
        float4 x = *reinterpret_cast<const float4*>(ApE);
        float4 y = *reinterpret_cast<const float4*>(ApE + 4);
        x.x*=inv; x.y*=inv; x.z*=inv; x.w*=inv;
        y.x*=inv; y.y*=inv; y.z*=inv; y.w*=inv;
        *reinterpret_cast<float4*>(ApE)     = x;
        *reinterpret_cast<float4*>(ApE + 4) = y;
        ra[0]=x.x; ra[1]=x.y; ra[2]=x.z; ra[3]=x.w; ra[4]=y.x; ra[5]=y.y; ra[6]=y.z; ra[7]=y.w;
        float2 v = *reinterpret_cast<const float2*>(Bp);
        rb[0]=v.x; rb[1]=v.y;
        cvt_store8(ra, &SA(0,0)[lrowA*LDg + lcolA], &SA(0,1)[lrowA*LDg + lcolA]);
        cvt_store2(rb, &SB(0,0)[lrowB*LDg + lcolB], &SB(0,1)[lrowB*LDg + lcolB]);
    }
    __syncthreads();

    for (int kt = 0; kt < KT; ++kt) {
        int cur = kt & 1;
        if (kt + 1 < KT) {
            float* pe = ApE + (kt + 1) * 16;
            float4 x = *reinterpret_cast<const float4*>(pe);
            float4 y = *reinterpret_cast<const float4*>(pe + 4);
            x.x*=inv; x.y*=inv; x.z*=inv; x.w*=inv;
            y.x*=inv; y.y*=inv; y.z*=inv; y.w*=inv;
            *reinterpret_cast<float4*>(pe)     = x;
            *reinterpret_cast<float4*>(pe + 4) = y;
            ra[0]=x.x; ra[1]=x.y; ra[2]=x.z; ra[3]=x.w; ra[4]=y.x; ra[5]=y.y; ra[6]=y.z; ra[7]=y.w;
            float2 v = *reinterpret_cast<const float2*>(Bp + (kt + 1) * 16);
            rb[0]=v.x; rb[1]=v.y;
        }
        mma_tile<2,4,LDg>(SA(cur,0), SA(cur,1), SB(cur,0), SB(cur,1),
                          wm * 32, wn * 32, g, t, c);
        if (kt + 1 < KT) {
            int nxt = cur ^ 1;
            cvt_store8(ra, &SA(nxt,0)[lrowA*LDg + lcolA], &SA(nxt,1)[lrowA*LDg + lcolA]);
            cvt_store2(rb, &SB(nxt,0)[lrowB*LDg + lcolB], &SB(nxt,1)[lrowB*LDg + lcolB]);
        }
        __syncthreads();
    }

    #pragma unroll
    for (int mi = 0; mi < 2; ++mi)
        #pragma unroll
        for (int nj = 0; nj < 4; ++nj)
            #pragma unroll
            for (int half = 0; half < 2; ++half) {
                int q = m0 + wm * 32 + mi * 16 + half * 8 + g;
                int d = wn * 32 + nj * 8 + 2 * t;
                float2 vv = make_float2(c[mi][nj][2*half], c[mi][nj][2*half + 1]);
                *reinterpret_cast<float2*>(
                    &g_O[((size_t)(b * Sc) + q) * HIDc + h * HDc + d]) = vv;
            }
    #undef SA
    #undef SB
}

// ---------------------------------------------------------------------------
extern "C" void kernel_launch(void* const* d_in, const int* in_sizes, int n_in,
                              void* d_out, int out_size)
{
    (void)in_sizes; (void)n_in; (void)out_size;
    const float* query = (const float*)d_in[0];
    const float* key   = (const float*)d_in[1];
    const float* value = (const float*)d_in[2];
    const int*   amask = (const int*)  d_in[3];
    const float* sim   = (const float*)d_in[4];
    const float* Wq    = (const float*)d_in[5];
    const float* bq    = (const float*)d_in[6];
    const float* Wk    = (const float*)d_in[7];
    const float* bk    = (const float*)d_in[8];
    const float* Wv    = (const float*)d_in[9];
    const float* bv    = (const float*)d_in[10];
    const float* Wo    = (const float*)d_in[11];
    const float* bo    = (const float*)d_in[12];
    const float* beta  = (const float*)d_in[13];

    float* out     = (float*)d_out;                      // [B,S,HID]
    float* weights = out + (size_t)Bc * Sc * HIDc;       // [B,NH,S,S]

    const int SCORES_SMEM = 4 * 128 * LDs * 2;                     // 73728 B
    const int AV_SMEM     = (2*2*256*LDg + 2*2*64*LDg) * 2;        // 61440 B

    static float *Qp = nullptr, *Kp = nullptr, *Vp = nullptr, *Op = nullptr;
    if (!Qp) {
        cudaGetSymbolAddress((void**)&Qp, g_Q);
        cudaGetSymbolAddress((void**)&Kp, g_K);
        cudaGetSymbolAddress((void**)&Vp, g_V);
        cudaGetSymbolAddress((void**)&Op, g_O);
        cudaFuncSetAttribute(scores_kernel,
            cudaFuncAttributeMaxDynamicSharedMemorySize, SCORES_SMEM);
        cudaFuncSetAttribute(av_kernel,
            cudaFuncAttributeMaxDynamicSharedMemorySize, AV_SMEM);
    }

    dim3 blk(512);
    dim3 gproj(HIDc / 128, BSc / 128);   // (8, 32)

    gemm_bf3_kernel<1><<<gproj, blk>>>(query, Wq, bq, Qp, BSc, HIDc, HIDc);
    gemm_bf3_kernel<1><<<gproj, blk>>>(key,   Wk, bk, Kp, BSc, HIDc, HIDc);
    gemm_bf3_kernel<2><<<gproj, blk>>>(value, Wv, bv, Vp, BSc, HIDc, HIDc);

    dim3 gsc(Sc / 128, Sc / 128, BHc);   // (16, 16, 32)
    scores_kernel<<<gsc, blk, SCORES_SMEM>>>(sim, amask, beta, weights);

    inv_kernel<<<(BHc * Sc) / 256, 256>>>();

    dim3 gav(Sc / 256, 1, BHc);          // (8, 1, 32)
    av_kernel<<<gav, blk, AV_SMEM>>>(weights);

    gemm_bf3_kernel<0><<<gproj, blk>>>(Op, Wo, bo, out, BSc, HIDc, HIDc);
}